// round 3
// baseline (speedup 1.0000x reference)
#include <cuda_runtime.h>
#include <math.h>
#include <stdint.h>

#define BHn   96
#define Nn    1024
#define Cc    64
#define RCc   32
#define RNn   128
#define NM1   1023
#define ROWS_TOT (BHn*NM1)   /* 98208 */
#define KTOP  16
#define BUDGET 256

// ---------------- scratch ----------------
__device__ __align__(16) float g_qp[BHn*Nn*RCc];
__device__ __align__(16) float g_kp[BHn*Nn*RCc];
__device__ __align__(16) float g_kp2p[8*BHn*RCc*RNn];
__device__ __align__(16) float g_kp2[BHn*RCc*RNn];
__device__ __align__(16) float g_basis[RNn*Nn];

typedef unsigned long long u64;
typedef unsigned u32;

// packed f32x2 helpers (bit-identical to scalar fma per component)
__device__ __forceinline__ void fma2(u64 &d, u64 a, u64 b) {
    asm("fma.rn.f32x2 %0, %1, %2, %0;" : "+l"(d) : "l"(a), "l"(b));
}
__device__ __forceinline__ u64 pk2(float x, float y) {
    u64 r; asm("mov.b64 %0, {%1, %2};" : "=l"(r) : "f"(x), "f"(y)); return r;
}
__device__ __forceinline__ void upk2(u64 v, float &x, float &y) {
    asm("mov.b64 {%0, %1}, %2;" : "=f"(x), "=f"(y) : "l"(v));
}

// ---------------- basis = Threshold(|proj_back_n.T|) ----------------
__global__ void k_basis(const float* __restrict__ pb) {
    int i = blockIdx.x*256 + threadIdx.x;
    if (i < RNn*Nn) {
        int j = i >> 7, c = i & 127;
        float v = fabsf(pb[i]);
        g_basis[(size_t)c*Nn + j] = (v > 0.02f) ? v : 0.0f;
    }
}

// ---------------- qp / kp projection ----------------
__global__ void k_proj(const float* __restrict__ x, const float* __restrict__ w,
                       const float* __restrict__ b, int which) {
    float* out = which ? g_kp : g_qp;
    int warp = threadIdx.x >> 5, lane = threadIdx.x & 31;
    int row0 = (blockIdx.x*8 + warp)*16;
    float wr[64];
    #pragma unroll
    for (int c4 = 0; c4 < 16; c4++) {
        float4 t = *(const float4*)(w + lane*64 + c4*4);
        wr[c4*4+0]=t.x; wr[c4*4+1]=t.y; wr[c4*4+2]=t.z; wr[c4*4+3]=t.w;
    }
    float bias = b[lane];
    for (int r = 0; r < 16; r++) {
        int row = row0 + r;
        float qlo = x[(size_t)row*64 + lane];
        float qhi = x[(size_t)row*64 + 32 + lane];
        float acc = 0.0f;
        #pragma unroll
        for (int c = 0; c < 32; c++) acc = fmaf(__shfl_sync(0xffffffffu, qlo, c), wr[c],    acc);
        #pragma unroll
        for (int c = 0; c < 32; c++) acc = fmaf(__shfl_sync(0xffffffffu, qhi, c), wr[32+c], acc);
        out[(size_t)row*32 + lane] = acc + bias;
    }
}

// ---------------- kp2 partial: smem tiles, rn-halved for occupancy ----------------
__global__ __launch_bounds__(256) void k_kp2_part(const float* __restrict__ proj_n) {
    __shared__ float kp_s[128*32];   // 16 KB
    __shared__ float pj_s[128*64];   // 32 KB
    int bh = blockIdx.x, ch = blockIdx.y, half = blockIdx.z;
    int n0 = ch*128, rnb = half*64, tid = threadIdx.x;
    const float4* src = (const float4*)(g_kp + ((size_t)bh*Nn + n0)*32);
    for (int i = tid; i < 1024; i += 256) ((float4*)kp_s)[i] = src[i];
    for (int i = tid; i < 2048; i += 256) {
        int r = i >> 4, c4 = i & 15;
        ((float4*)pj_s)[i] = *((const float4*)(proj_n + (size_t)(n0+r)*128 + rnb) + c4);
    }
    __syncthreads();
    int rc0 = (tid & 7)*4;
    int rn0 = (tid >> 3)*2;
    float a00=0,a01=0,a10=0,a11=0,a20=0,a21=0,a30=0,a31=0;
    #pragma unroll 4
    for (int n = 0; n < 128; n++) {
        float4 a = *(const float4*)(kp_s + n*32 + rc0);
        float2 p = *(const float2*)(pj_s + n*64 + rn0);
        a00 = fmaf(a.x, p.x, a00); a01 = fmaf(a.x, p.y, a01);
        a10 = fmaf(a.y, p.x, a10); a11 = fmaf(a.y, p.y, a11);
        a20 = fmaf(a.z, p.x, a20); a21 = fmaf(a.z, p.y, a21);
        a30 = fmaf(a.w, p.x, a30); a31 = fmaf(a.w, p.y, a31);
    }
    float* outp = g_kp2p + ((size_t)ch*BHn + bh)*4096 + rnb + rn0;
    *(float2*)(outp + (rc0+0)*128) = make_float2(a00, a01);
    *(float2*)(outp + (rc0+1)*128) = make_float2(a10, a11);
    *(float2*)(outp + (rc0+2)*128) = make_float2(a20, a21);
    *(float2*)(outp + (rc0+3)*128) = make_float2(a30, a31);
}

__global__ void k_kp2_red() {
    int i = blockIdx.x*256 + threadIdx.x;
    if (i < BHn*RCc*RNn) {
        float s = 0.0f;
        #pragma unroll
        for (int ch = 0; ch < 8; ch++) s += g_kp2p[(size_t)ch*BHn*4096 + i];
        g_kp2[i] = s;
    }
}

// ---------------- fused: cheap_attn + softmax + topk16 + sparse SpMM + top-256 mask ----------------
__global__ __launch_bounds__(256) void k_main(float* __restrict__ out_coef,
                                              float* __restrict__ out_approx,
                                              float* __restrict__ out_mask) {
    __shared__ u64 sm_pair[8][16];   // (idx<<32)|valbits, ordered by ascending idx
    __shared__ u32 sm_cand[8][32];   // compacted selection candidates
    int warp = threadIdx.x >> 5, lane = threadIdx.x & 31;
    const unsigned FULL = 0xffffffffu;
    int rr = blockIdx.x*8 + warp;
    int bh = rr / NM1;
    int n  = rr - bh*NM1 + 1;

    // ---- cheap attn row (128 logits; 4 per lane) ----
    float qv = g_qp[((size_t)bh*Nn + n)*32 + lane];
    const float4* kb = (const float4*)(g_kp2 + (size_t)bh*4096);
    float4 accq = {0.f,0.f,0.f,0.f};
    #pragma unroll
    for (int rc = 0; rc < 32; rc++) {
        float a = __shfl_sync(FULL, qv, rc);
        float4 kv = __ldg(kb + rc*32 + lane);
        accq.x = fmaf(a, kv.x, accq.x);
        accq.y = fmaf(a, kv.y, accq.y);
        accq.z = fmaf(a, kv.z, accq.z);
        accq.w = fmaf(a, kv.w, accq.w);
    }
    const float scale = 0.28867513459481287f;   // 12^-0.5
    float l[4] = {accq.x*scale, accq.y*scale, accq.z*scale, accq.w*scale};
    float m = fmaxf(fmaxf(l[0], l[1]), fmaxf(l[2], l[3]));
    #pragma unroll
    for (int off = 16; off; off >>= 1) m = fmaxf(m, __shfl_xor_sync(FULL, m, off));
    float e[4], s = 0.0f;
    #pragma unroll
    for (int j = 0; j < 4; j++) { e[j] = expf(l[j] - m); s += e[j]; }
    #pragma unroll
    for (int off = 16; off; off >>= 1) s += __shfl_xor_sync(FULL, s, off);
    float c[4];
    #pragma unroll
    for (int j = 0; j < 4; j++) c[j] = e[j] / s;

    // ---- topk16 of 128 (desc value, tie -> lower idx) ----
    unsigned rem = 0xFu, sel = 0u;
    float myv = 0.0f; int myi = 0;
    for (int t = 0; t < 16; t++) {
        float bv = -1.0f; int bi = 0x7fffffff;
        #pragma unroll
        for (int j = 0; j < 4; j++) {
            if (rem & (1u << j)) {
                float v = c[j]; int idx = lane*4 + j;
                if (v > bv || (v == bv && idx < bi)) { bv = v; bi = idx; }
            }
        }
        #pragma unroll
        for (int off = 16; off; off >>= 1) {
            float ov = __shfl_xor_sync(FULL, bv, off);
            int   oi = __shfl_xor_sync(FULL, bi, off);
            if (ov > bv || (ov == bv && oi < bi)) { bv = ov; bi = oi; }
        }
        if ((bi >> 2) == lane) { rem &= ~(1u << (bi & 3)); sel |= (1u << (bi & 3)); }
        if (lane == t) { myv = bv; myi = bi; }
    }
    // rank by ascending basis index (matches reference accumulation order)
    int rank = 0;
    #pragma unroll
    for (int u = 0; u < 16; u++) {
        int oi = __shfl_sync(FULL, myi, u);
        if (u != lane && oi < myi) rank++;
    }
    if (lane < 16)
        sm_pair[warp][rank] = ((u64)(unsigned)myi << 32) | (u64)__float_as_uint(myv);

    // dense basis_coef row
    {
        float4 o;
        o.x = (sel & 1u) ? c[0] : 0.0f;
        o.y = (sel & 2u) ? c[1] : 0.0f;
        o.z = (sel & 4u) ? c[2] : 0.0f;
        o.w = (sel & 8u) ? c[3] : 0.0f;
        *(float4*)(out_coef + (size_t)rr*128 + lane*4) = o;
    }
    __syncwarp();

    // ---- sparse SpMM: acc = sum over 16 selected basis rows (ascending idx) ----
    u64 acc[16];
    #pragma unroll
    for (int j = 0; j < 16; j++) acc[j] = 0ULL;
    #pragma unroll 4
    for (int t = 0; t < 16; t++) {
        u64 pr = sm_pair[warp][t];
        int   ci = (int)(pr >> 32);
        float v  = __uint_as_float((u32)pr);
        u64 vv = pk2(v, v);
        const float4* bp = (const float4*)g_basis + (size_t)ci*256;
        #pragma unroll
        for (int j = 0; j < 8; j++) {
            float4 x = __ldg(bp + j*32 + lane);
            fma2(acc[2*j],   pk2(x.x, x.y), vv);
            fma2(acc[2*j+1], pk2(x.z, x.w), vv);
        }
    }

    // write approx_attn (streaming)
    float* outp = out_approx + (size_t)rr*1024;
    #pragma unroll
    for (int j = 0; j < 8; j++) {
        float4 o;
        upk2(acc[2*j],   o.x, o.y);
        upk2(acc[2*j+1], o.z, o.w);
        __stcs((float4*)outp + j*32 + lane, o);
    }

    // ---- exact top-256 threshold: register-hist 4-bit radix + ballot finish ----
    unsigned prefix = 0u; int k = BUDGET; int shift = 32; int mm = 1024;
    for (int p = 0; p < 8; p++) {
        shift -= 4;
        u64 h0 = 0ULL, h1 = 0ULL;
        #pragma unroll
        for (int i = 0; i < 16; i++) {
            u64 a = acc[i];
            #pragma unroll
            for (int hv = 0; hv < 2; hv++) {
                unsigned u = (unsigned)(a >> (hv*32));
                bool match = (p == 0) || ((u >> (shift+4)) == (prefix >> (shift+4)));
                int bin = (u >> shift) & 15;
                u64 inc = 1ULL << ((bin & 7) << 3);
                if (match) { if (bin < 8) h0 += inc; else h1 += inc; }
            }
        }
        // warp reduce byte counters (2 steps, max 128/byte), expand to 16-bit, 3 more steps
        h0 += __shfl_xor_sync(FULL, h0, 1); h1 += __shfl_xor_sync(FULL, h1, 1);
        h0 += __shfl_xor_sync(FULL, h0, 2); h1 += __shfl_xor_sync(FULL, h1, 2);
        const u64 MB = 0x00FF00FF00FF00FFULL;
        u64 e0 = h0 & MB, o0 = (h0 >> 8) & MB;
        u64 e1 = h1 & MB, o1 = (h1 >> 8) & MB;
        #pragma unroll
        for (int off = 4; off <= 16; off <<= 1) {
            e0 += __shfl_xor_sync(FULL, e0, off);
            o0 += __shfl_xor_sync(FULL, o0, off);
            e1 += __shfl_xor_sync(FULL, e1, off);
            o1 += __shfl_xor_sync(FULL, o1, off);
        }
        // lane b (<16) extracts count[b]; suffix-sum from high bins
        int b = lane & 15;
        u64 srcw = (b < 8) ? ((b & 1) ? o0 : e0) : ((b & 1) ? o1 : e1);
        unsigned cntb = (unsigned)((srcw >> (((b >> 1) & 3)*16)) & 0xFFFFu);
        unsigned S = cntb;
        #pragma unroll
        for (int off = 1; off <= 8; off <<= 1) {
            unsigned v = __shfl_down_sync(FULL, S, off);
            if (lane + off < 16) S += v;
        }
        bool hit = (lane < 16) && (S >= (unsigned)k) && (S - cntb < (unsigned)k);
        unsigned bal = __ballot_sync(FULL, hit);
        int bsel = __ffs(bal) - 1;
        unsigned S_s   = __shfl_sync(FULL, S,    bsel);
        unsigned cnt_s = __shfl_sync(FULL, cntb, bsel);
        prefix |= ((unsigned)bsel) << shift;
        k -= (int)(S_s - cnt_s);
        mm = (int)cnt_s;
        if (mm <= 32 || shift == 0) break;
    }
    if (shift > 0) {
        // compact candidates (<=32) to one per lane, then bit-descent with ballot counts
        unsigned cmpv = prefix >> shift;
        unsigned ltm = (1u << lane) - 1u;
        int base = 0;
        u32* sb = sm_cand[warp];
        #pragma unroll
        for (int i = 0; i < 16; i++) {
            u64 a = acc[i];
            #pragma unroll
            for (int hv = 0; hv < 2; hv++) {
                unsigned u = (unsigned)(a >> (hv*32));
                bool f = (u >> shift) == cmpv;
                unsigned bal = __ballot_sync(FULL, f);
                if (f) sb[base + __popc(bal & ltm)] = u;
                base += __popc(bal);
            }
        }
        __syncwarp();
        bool valid = lane < base;
        unsigned cand = sb[lane & 31];
        unsigned thr = prefix;
        for (int bb = shift - 1; bb >= 0; bb--) {
            unsigned t2 = thr | (1u << bb);
            int cgt = __popc(__ballot_sync(FULL, valid && cand >= t2));
            if (cgt >= k) thr = t2;
        }
        prefix = thr;
    }

    // ---- mask row: u >= prefix ----
    float* mout = out_mask + ((size_t)bh*Nn + n)*Nn;
    #pragma unroll
    for (int j = 0; j < 8; j++) {
        unsigned u0 = (unsigned)(acc[2*j]);
        unsigned u1 = (unsigned)(acc[2*j] >> 32);
        unsigned u2 = (unsigned)(acc[2*j+1]);
        unsigned u3 = (unsigned)(acc[2*j+1] >> 32);
        float4 mo;
        mo.x = (u0 >= prefix) ? 1.0f : 0.0f;
        mo.y = (u1 >= prefix) ? 1.0f : 0.0f;
        mo.z = (u2 >= prefix) ? 1.0f : 0.0f;
        mo.w = (u3 >= prefix) ? 1.0f : 0.0f;
        __stcs((float4*)mout + j*32 + lane, mo);
    }
}

// ---------------- cls rows ----------------
__global__ void k_cls(float* __restrict__ out_mask) {
    size_t bh = blockIdx.x;
    for (int j = threadIdx.x; j < Nn; j += 256)
        out_mask[bh*Nn*Nn + j] = 1.0f;
}

// ---------------- launch ----------------
extern "C" void kernel_launch(void* const* d_in, const int* in_sizes, int n_in,
                              void* d_out, int out_size) {
    const float* q  = (const float*)d_in[0];
    const float* k  = (const float*)d_in[1];
    const float* wq = (const float*)d_in[2];
    const float* bq = (const float*)d_in[3];
    const float* wk = (const float*)d_in[4];
    const float* bk = (const float*)d_in[5];
    const float* pn = (const float*)d_in[6];
    const float* pb = (const float*)d_in[7];

    float* out        = (float*)d_out;
    float* out_coef   = out;
    float* out_approx = out + (size_t)ROWS_TOT*RNn;
    float* out_mask   = out_approx + (size_t)ROWS_TOT*Nn;

    k_basis<<<512, 256>>>(pb);
    k_proj<<<768, 256>>>(q, wq, bq, 0);
    k_proj<<<768, 256>>>(k, wk, bk, 1);
    k_kp2_part<<<dim3(BHn, 8, 2), 256>>>(pn);
    k_kp2_red<<<1536, 256>>>();
    k_main<<<ROWS_TOT/8, 256>>>(out_coef, out_approx, out_mask);
    k_cls<<<BHn, 256>>>(out_mask);
}